// round 2
// baseline (speedup 1.0000x reference)
#include <cuda_runtime.h>

// Problem constants
#define CB 2
#define CS 2048
#define CE 1024
#define CH 16
#define CDK 64
#define CM (CB * CS)   // 4096 rows

// Scratch (allocation-free: __device__ globals)
__device__ float g_q[CB * CH * CS * CDK];    // [b,h,s,d]
__device__ float g_k[CB * CH * CS * CDK];
__device__ float g_v[CB * CH * CS * CDK];
__device__ float g_att[CB * CS * CE];        // [b,s,e]

// ---------------------------------------------------------------------------
// GEMM: C = A[M,K] @ W[N,K]^T + bias[N]
// PERM=1: scatter output into [b,h,s,d] layout; PERM=0: row-major [M,N].
// Tiles: BM=BN=64, BK=16; 256 threads; 4x4 micro-tile per thread.
// ---------------------------------------------------------------------------
template <int PERM>
__global__ void __launch_bounds__(256) gemm_bias_kernel(
    const float* __restrict__ A, const float* __restrict__ W,
    const float* __restrict__ bias, float* __restrict__ C,
    int M, int N, int K)
{
    __shared__ float As[64][17];
    __shared__ float Ws[64][17];

    const int tid = threadIdx.x;
    const int ty = tid >> 4;        // 0..15 (row group)
    const int tx = tid & 15;        // 0..15 (col group)
    const int m0 = blockIdx.y * 64;
    const int n0 = blockIdx.x * 64;

    const int lr  = tid >> 2;       // 0..63 row for tile load
    const int lc4 = tid & 3;        // 0..3 float4 slot within 16-wide K

    float acc[4][4];
    #pragma unroll
    for (int i = 0; i < 4; i++)
        #pragma unroll
        for (int j = 0; j < 4; j++) acc[i][j] = 0.f;

    for (int k0 = 0; k0 < K; k0 += 16) {
        float4 av = *(const float4*)(A + (size_t)(m0 + lr) * K + k0 + lc4 * 4);
        float4 wv = *(const float4*)(W + (size_t)(n0 + lr) * K + k0 + lc4 * 4);
        As[lr][lc4 * 4 + 0] = av.x; As[lr][lc4 * 4 + 1] = av.y;
        As[lr][lc4 * 4 + 2] = av.z; As[lr][lc4 * 4 + 3] = av.w;
        Ws[lr][lc4 * 4 + 0] = wv.x; Ws[lr][lc4 * 4 + 1] = wv.y;
        Ws[lr][lc4 * 4 + 2] = wv.z; Ws[lr][lc4 * 4 + 3] = wv.w;
        __syncthreads();

        #pragma unroll
        for (int k = 0; k < 16; k++) {
            float a[4], w[4];
            #pragma unroll
            for (int i = 0; i < 4; i++) a[i] = As[ty * 4 + i][k];
            #pragma unroll
            for (int j = 0; j < 4; j++) w[j] = Ws[tx * 4 + j][k];
            #pragma unroll
            for (int i = 0; i < 4; i++)
                #pragma unroll
                for (int j = 0; j < 4; j++)
                    acc[i][j] = fmaf(a[i], w[j], acc[i][j]);
        }
        __syncthreads();
    }

    #pragma unroll
    for (int i = 0; i < 4; i++) {
        const int m = m0 + ty * 4 + i;
        #pragma unroll
        for (int j = 0; j < 4; j++) {
            const int n = n0 + tx * 4 + j;
            const float val = acc[i][j] + bias[n];
            if (PERM) {
                // m = b*S + s ; n = h*DK + d  -> ((b*H+h)*S + s)*DK + d
                const int b = m >> 11, s = m & 2047;
                const int h = n >> 6,  d = n & 63;
                C[(((size_t)(b * CH + h) * CS + s) * CDK) + d] = val;
            } else {
                C[(size_t)m * N + n] = val;
            }
        }
    }
}

// ---------------------------------------------------------------------------
// Flash-style causal attention over [b,h,s,d] projected tensors.
// Grid: (S/64 query tiles, B*H). Block: 256 threads.
// Each thread: row = tid/4 (query within tile), owns 16 contiguous d-slots
// (tc*16..tc*16+15) of the output and 16 strided score columns (j*4+tc).
// smem: Q/K/V/P tiles, 64 rows x stride-68 floats (conflict-free float4).
// ---------------------------------------------------------------------------
__global__ void __launch_bounds__(256) attn_kernel(
    const float* __restrict__ Q, const float* __restrict__ K,
    const float* __restrict__ V, float* __restrict__ O)
{
    extern __shared__ float sm[];
    float* Qs = sm;                 // [64][68]
    float* Ks = sm + 64 * 68;
    float* Vs = sm + 2 * 64 * 68;
    float* Ps = sm + 3 * 64 * 68;

    const int qt  = blockIdx.x;
    const int bh  = blockIdx.y;
    const int tid = threadIdx.x;
    const int row = tid >> 2;       // 0..63
    const int tc  = tid & 3;        // 0..3

    const size_t base = (size_t)bh * CS * CDK;
    const float* Qb = Q + base + (size_t)qt * 64 * CDK;

    // Load Q tile (coalesced float4)
    #pragma unroll
    for (int i = 0; i < 4; i++) {
        const int idx = tid + i * 256;          // 0..1023 float4 slots
        const int r = idx >> 4, c4 = idx & 15;
        float4 t = *(const float4*)(Qb + r * 64 + c4 * 4);
        float* d = Qs + r * 68 + c4 * 4;
        d[0] = t.x; d[1] = t.y; d[2] = t.z; d[3] = t.w;
    }

    float mrun = -1e30f, lrun = 0.f;
    float acc[16];
    #pragma unroll
    for (int i = 0; i < 16; i++) acc[i] = 0.f;

    const int qg = qt * 64 + row;   // global query index

    for (int kt = 0; kt <= qt; kt++) {
        __syncthreads();            // previous PV reads of Ks/Vs done
        const float* Kb = K + base + (size_t)kt * 64 * CDK;
        const float* Vb = V + base + (size_t)kt * 64 * CDK;
        #pragma unroll
        for (int i = 0; i < 4; i++) {
            const int idx = tid + i * 256;
            const int r = idx >> 4, c4 = idx & 15;
            float4 t = *(const float4*)(Kb + r * 64 + c4 * 4);
            float* d = Ks + r * 68 + c4 * 4;
            d[0] = t.x; d[1] = t.y; d[2] = t.z; d[3] = t.w;
            float4 t2 = *(const float4*)(Vb + r * 64 + c4 * 4);
            float* d2 = Vs + r * 68 + c4 * 4;
            d2[0] = t2.x; d2[1] = t2.y; d2[2] = t2.z; d2[3] = t2.w;
        }
        __syncthreads();

        // Scores: sc[j] = <Q[row,:], K[col(j),:]> with col(j) = j*4 + tc
        float sc[16];
        #pragma unroll
        for (int j = 0; j < 16; j++) sc[j] = 0.f;
        #pragma unroll 4
        for (int d4 = 0; d4 < 16; d4++) {
            const float4 qv = *(const float4*)(Qs + row * 68 + d4 * 4);
            #pragma unroll
            for (int j = 0; j < 16; j++) {
                const float4 kv =
                    *(const float4*)(Ks + ((j << 2) | tc) * 68 + d4 * 4);
                float s = sc[j];
                s = fmaf(qv.x, kv.x, s);
                s = fmaf(qv.y, kv.y, s);
                s = fmaf(qv.z, kv.z, s);
                s = fmaf(qv.w, kv.w, s);
                sc[j] = s;
            }
        }

        // Scale + causal mask (diagonal tile only), tile max
        const bool diag = (kt == qt);
        float tmax = -1e30f;
        #pragma unroll
        for (int j = 0; j < 16; j++) {
            const int col = (j << 2) | tc;
            float s = sc[j] * 0.125f;   // 1/sqrt(64)
            if (diag && (kt * 64 + col) > qg) s = -1e30f;
            sc[j] = s;
            tmax = fmaxf(tmax, s);
        }
        tmax = fmaxf(tmax, __shfl_xor_sync(0xffffffffu, tmax, 1));
        tmax = fmaxf(tmax, __shfl_xor_sync(0xffffffffu, tmax, 2));

        // Online softmax update
        const float mnew = fmaxf(mrun, tmax);
        const float corr = __expf(mrun - mnew);
        lrun *= corr;
        #pragma unroll
        for (int i = 0; i < 16; i++) acc[i] *= corr;

        float ps = 0.f;
        #pragma unroll
        for (int j = 0; j < 16; j++) {
            const float p = __expf(sc[j] - mnew);
            ps += p;
            Ps[row * 68 + ((j << 2) | tc)] = p;
        }
        ps += __shfl_xor_sync(0xffffffffu, ps, 1);
        ps += __shfl_xor_sync(0xffffffffu, ps, 2);
        lrun += ps;
        mrun = mnew;
        __syncthreads();            // Ps visible to all 4 threads of each row

        // PV: acc[d] += sum_j P[row,j] * V[j,d], d = tc*16 + dd
        #pragma unroll 4
        for (int j = 0; j < 64; j++) {
            const float p = Ps[row * 68 + j];
            const float* vp = Vs + j * 68 + tc * 16;
            #pragma unroll
            for (int s4 = 0; s4 < 4; s4++) {
                const float4 vv = *(const float4*)(vp + s4 * 4);
                acc[s4 * 4 + 0] = fmaf(p, vv.x, acc[s4 * 4 + 0]);
                acc[s4 * 4 + 1] = fmaf(p, vv.y, acc[s4 * 4 + 1]);
                acc[s4 * 4 + 2] = fmaf(p, vv.z, acc[s4 * 4 + 2]);
                acc[s4 * 4 + 3] = fmaf(p, vv.w, acc[s4 * 4 + 3]);
            }
        }
    }

    // Epilogue: normalize and write [b,s,e] layout
    const float inv = 1.0f / lrun;
    const int b = bh >> 4, h = bh & 15;
    float* Ob = O + ((size_t)(b * CS + qg) * CE) + h * CDK + tc * 16;
    #pragma unroll
    for (int s4 = 0; s4 < 4; s4++) {
        float4 o;
        o.x = acc[s4 * 4 + 0] * inv;
        o.y = acc[s4 * 4 + 1] * inv;
        o.z = acc[s4 * 4 + 2] * inv;
        o.w = acc[s4 * 4 + 3] * inv;
        *(float4*)(Ob + s4 * 4) = o;
    }
}

// ---------------------------------------------------------------------------
// Launcher
// Inputs (metadata order): q, k, v, mask, w_q, b_q, w_k, b_k, w_v, b_v, w_o, b_o
// ---------------------------------------------------------------------------
extern "C" void kernel_launch(void* const* d_in, const int* in_sizes, int n_in,
                              void* d_out, int out_size)
{
    (void)in_sizes; (void)n_in; (void)out_size;
    const float* q   = (const float*)d_in[0];
    const float* k   = (const float*)d_in[1];
    const float* v   = (const float*)d_in[2];
    // d_in[3] = mask (causal tril, implemented structurally)
    const float* w_q = (const float*)d_in[4];
    const float* b_q = (const float*)d_in[5];
    const float* w_k = (const float*)d_in[6];
    const float* b_k = (const float*)d_in[7];
    const float* w_v = (const float*)d_in[8];
    const float* b_v = (const float*)d_in[9];
    const float* w_o = (const float*)d_in[10];
    const float* b_o = (const float*)d_in[11];
    float* out = (float*)d_out;

    float *pq, *pk, *pv, *patt;
    cudaGetSymbolAddress((void**)&pq, g_q);
    cudaGetSymbolAddress((void**)&pk, g_k);
    cudaGetSymbolAddress((void**)&pv, g_v);
    cudaGetSymbolAddress((void**)&patt, g_att);

    const dim3 gg(CE / 64, CM / 64);   // (16, 64)

    gemm_bias_kernel<1><<<gg, 256>>>(q, w_q, b_q, pq, CM, CE, CE);
    gemm_bias_kernel<1><<<gg, 256>>>(k, w_k, b_k, pk, CM, CE, CE);
    gemm_bias_kernel<1><<<gg, 256>>>(v, w_v, b_v, pv, CM, CE, CE);

    const int smem_bytes = 4 * 64 * 68 * (int)sizeof(float);   // 69632
    cudaFuncSetAttribute(attn_kernel,
                         cudaFuncAttributeMaxDynamicSharedMemorySize,
                         smem_bytes);
    attn_kernel<<<dim3(CS / 64, CB * CH), 256, smem_bytes>>>(pq, pk, pv, patt);

    gemm_bias_kernel<0><<<gg, 256>>>(patt, w_o, b_o, out, CM, CE, CE);
}